// round 6
// baseline (speedup 1.0000x reference)
#include <cuda_runtime.h>
#include <cuda_bf16.h>
#include <cstdint>

#define BB 32
#define NNODE 8192
#define DDIM 8
#define PPART 64
#define WWID 128
#define TTEMP 8
#define LL2 32
#define I2D 2320
#define KDIM 1024

// scratch (no allocs allowed)
__device__ __align__(256) float g_base[PPART * I2D];                // b1 + cap@W2
__device__ __align__(256) float g_h[(size_t)PPART * BB * I2D];      // h as [p][b][o]
__device__ __align__(256) float g_zp[PPART * 8 * BB * WWID];        // split-K partials
__device__ __align__(256) float g_wx[BB * PPART * DDIM];            // [b][p][d]

// ---------------- helpers (SIMT path, k_z) ----------------
__device__ __forceinline__ unsigned long long ffma2(unsigned long long a,
                                                    unsigned long long b,
                                                    unsigned long long c) {
    unsigned long long d;
    asm("fma.rn.f32x2 %0, %1, %2, %3;" : "=l"(d) : "l"(a), "l"(b), "l"(c));
    return d;
}
__device__ __forceinline__ float flo(unsigned long long v) { return __uint_as_float((unsigned)v); }
__device__ __forceinline__ float fhi(unsigned long long v) { return __uint_as_float((unsigned)(v >> 32)); }
__device__ __forceinline__ void cp16(uint32_t dst, const void* src, int szb) {
    asm volatile("cp.async.cg.shared.global [%0], [%1], 16, %2;\n" :: "r"(dst), "l"(src), "r"(szb));
}
__device__ __forceinline__ void cp_commit() { asm volatile("cp.async.commit_group;\n"); }
__device__ __forceinline__ void cp_wait1()  { asm volatile("cp.async.wait_group 1;\n"); }

// ---------------- mma.sync helpers ----------------
#define LDMX4(r, addr) \
    asm volatile("ldmatrix.sync.aligned.m8n8.x4.shared.b16 {%0,%1,%2,%3}, [%4];" \
                 : "=r"((r)[0]), "=r"((r)[1]), "=r"((r)[2]), "=r"((r)[3]) : "r"(addr))

#define MMA16816(d, a, b0, b1) \
    asm volatile("mma.sync.aligned.m16n8k16.row.col.f32.bf16.bf16.f32 " \
                 "{%0,%1,%2,%3}, {%4,%5,%6,%7}, {%8,%9}, {%0,%1,%2,%3};" \
                 : "+f"((d)[0]), "+f"((d)[1]), "+f"((d)[2]), "+f"((d)[3]) \
                 : "r"((a)[0]), "r"((a)[1]), "r"((a)[2]), "r"((a)[3]), "r"(b0), "r"(b1))

#define STS128(addr, r0, r1, r2, r3) \
    asm volatile("st.shared.v4.b32 [%0], {%1,%2,%3,%4};" \
                 :: "r"(addr), "r"(r0), "r"(r1), "r"(r2), "r"(r3) : "memory")

__device__ __forceinline__ uint32_t bfpair(float a, float b) {
    __nv_bfloat162 h = __floats2bfloat162_rn(a, b);
    return *(uint32_t*)&h;
}
__device__ __forceinline__ float bflo(uint32_t u) {
    return __bfloat162float(*(__nv_bfloat16*)&u);
}
__device__ __forceinline__ float bfhi(uint32_t u) {
    uint16_t h = (uint16_t)(u >> 16);
    return __bfloat162float(*(__nv_bfloat16*)&h);
}

// ========== kernel 1: base[p,o] = b1 + cap(p)·W2[p,o,:] ==========
__global__ void k_base(const float* __restrict__ W2, const float* __restrict__ b1,
                       const float* __restrict__ cap) {
    int idx = blockIdx.x * 8 + (threadIdx.x >> 5);
    if (idx >= PPART * I2D) return;
    int p = idx / I2D, lane = threadIdx.x & 31;
    float4 wv = *(const float4*)(W2 + (size_t)idx * WWID + lane * 4);
    float4 cv = *(const float4*)(cap + p * WWID + lane * 4);
    float acc = wv.x * cv.x + wv.y * cv.y + wv.z * cv.z + wv.w * cv.w;
    #pragma unroll
    for (int o = 16; o > 0; o >>= 1) acc += __shfl_xor_sync(0xffffffffu, acc, o);
    if (lane == 0) g_base[idx] = acc + b1[idx];
}

// ========== kernel 2: h via mma.sync bf16 3-pass split (no spills: 2 CTAs/SM) ==========
#define PITCHB 40                     // bf16 per row (80 B): conflict-free
#define A_TILE (128 * PITCHB * 2)     // 10240 B
#define B_TILE (32 * PITCHB * 2)      // 2560 B
#define OFF_AH 0
#define OFF_AL A_TILE
#define OFF_BH (2 * A_TILE)
#define OFF_BL (2 * A_TILE + B_TILE)
#define STAGE  (2 * A_TILE + 2 * B_TILE)   // 25600 B

__global__ void __launch_bounds__(128, 2)
k_main_mma(const float* __restrict__ W0, const float* __restrict__ x,
           const float* __restrict__ t, const float* __restrict__ W1,
           const int* __restrict__ nodes) {
    const int p = blockIdx.y, m0 = blockIdx.x * 128;
    const int tid = threadIdx.x, w = tid >> 5, lane = tid & 31;
    extern __shared__ char sm[];
    __shared__ float s_t[BB * 9];
    __shared__ int s_nodes[WWID];
    const uint32_t smb = (uint32_t)__cvta_generic_to_shared(sm);

    for (int i = tid; i < BB * TTEMP; i += 128) s_t[(i >> 3) * 9 + (i & 7)] = t[i];
    if (tid < WWID) s_nodes[tid] = nodes[p * WWID + tid];
    __syncthreads();

    // A: thread owns one W0 row (clamped); B: thread owns (row=tid>>2, 8-col seg)
    const float* W0row = W0 + (size_t)p * I2D * KDIM +
                         (size_t)((m0 + tid < I2D) ? (m0 + tid) : (I2D - 1)) * KDIM;
    const int brow = tid >> 2, bseg = tid & 3;
    const float* xrow = x + (size_t)brow * (NNODE * DDIM);

    float4 ra[8];
    float4 rb[2];
    #pragma unroll
    for (int q = 0; q < 8; q++) ra[q] = *(const float4*)(W0row + q * 4);
    {
        int node = s_nodes[bseg];
        rb[0] = *(const float4*)(xrow + node * 8);
        rb[1] = *(const float4*)(xrow + node * 8 + 4);
    }

    float acc[2][4][4];
    #pragma unroll
    for (int i = 0; i < 2; i++)
        #pragma unroll
        for (int j = 0; j < 4; j++)
            #pragma unroll
            for (int r = 0; r < 4; r++) acc[i][j][r] = 0.f;

    for (int c = 0; c < 32; c++) {
        const uint32_t bufo = smb + (uint32_t)(c & 1) * STAGE;

        // ---- convert + store A (this thread's row, 32 cols) ----
        {
            uint32_t abh = bufo + OFF_AH + (uint32_t)tid * (PITCHB * 2);
            uint32_t abl = bufo + OFF_AL + (uint32_t)tid * (PITCHB * 2);
            #pragma unroll
            for (int qq = 0; qq < 4; qq++) {
                float4 v0 = ra[qq * 2], v1 = ra[qq * 2 + 1];
                uint32_t h0 = bfpair(v0.x, v0.y), h1 = bfpair(v0.z, v0.w);
                uint32_t h2 = bfpair(v1.x, v1.y), h3 = bfpair(v1.z, v1.w);
                uint32_t l0 = bfpair(v0.x - bflo(h0), v0.y - bfhi(h0));
                uint32_t l1 = bfpair(v0.z - bflo(h1), v0.w - bfhi(h1));
                uint32_t l2 = bfpair(v1.x - bflo(h2), v1.y - bfhi(h2));
                uint32_t l3 = bfpair(v1.z - bflo(h3), v1.w - bfhi(h3));
                STS128(abh + qq * 16, h0, h1, h2, h3);
                STS128(abl + qq * 16, l0, l1, l2, l3);
            }
        }
        // ---- convert + store B (row brow, cols bseg*8..+7) ----
        {
            uint32_t bbh = bufo + OFF_BH + (uint32_t)(brow * (PITCHB * 2) + bseg * 16);
            float4 v0 = rb[0], v1 = rb[1];
            uint32_t h0 = bfpair(v0.x, v0.y), h1 = bfpair(v0.z, v0.w);
            uint32_t h2 = bfpair(v1.x, v1.y), h3 = bfpair(v1.z, v1.w);
            uint32_t l0 = bfpair(v0.x - bflo(h0), v0.y - bfhi(h0));
            uint32_t l1 = bfpair(v0.z - bflo(h1), v0.w - bfhi(h1));
            uint32_t l2 = bfpair(v1.x - bflo(h2), v1.y - bfhi(h2));
            uint32_t l3 = bfpair(v1.z - bflo(h3), v1.w - bfhi(h3));
            STS128(bbh, h0, h1, h2, h3);
            STS128(bbh + (OFF_BL - OFF_BH), l0, l1, l2, l3);
        }

        // ---- prefetch chunk c+1 into ra/rb (overlaps with sync+mma) ----
        {
            int cn = (c < 31) ? (c + 1) : 31;
            #pragma unroll
            for (int q = 0; q < 8; q++)
                ra[q] = *(const float4*)(W0row + cn * 32 + q * 4);
            int node = s_nodes[cn * 4 + bseg];
            rb[0] = *(const float4*)(xrow + node * 8);
            rb[1] = *(const float4*)(xrow + node * 8 + 4);
        }

        __syncthreads();

        // ---- MMA: 2 ksteps of k16, 3 passes (hh, hl, lh) ----
        #pragma unroll
        for (int s = 0; s < 2; s++) {
            uint32_t Ah[2][4], Al[2][4], Bh[2][4], Bl[2][4];
            #pragma unroll
            for (int i = 0; i < 2; i++) {
                int row = w * 32 + i * 16 + (lane & 7) + ((lane >> 3) & 1) * 8;
                int col = s * 16 + (lane >> 4) * 8;
                uint32_t ah = bufo + OFF_AH + (uint32_t)(row * PITCHB + col) * 2;
                LDMX4(Ah[i], ah);
                LDMX4(Al[i], ah + (OFF_AL - OFF_AH));
            }
            #pragma unroll
            for (int q = 0; q < 2; q++) {
                int row = q * 16 + (lane >> 4) * 8 + (lane & 7);
                int col = s * 16 + ((lane >> 3) & 1) * 8;
                uint32_t bh = bufo + OFF_BH + (uint32_t)(row * PITCHB + col) * 2;
                LDMX4(Bh[q], bh);
                LDMX4(Bl[q], bh + (OFF_BL - OFF_BH));
            }
            #pragma unroll
            for (int j = 0; j < 4; j++) {
                uint32_t b0h = Bh[j >> 1][(j & 1) * 2], b1h = Bh[j >> 1][(j & 1) * 2 + 1];
                uint32_t b0l = Bl[j >> 1][(j & 1) * 2], b1l = Bl[j >> 1][(j & 1) * 2 + 1];
                #pragma unroll
                for (int i = 0; i < 2; i++) {
                    MMA16816(acc[i][j], Ah[i], b0h, b1h);
                    MMA16816(acc[i][j], Ah[i], b0l, b1l);
                    MMA16816(acc[i][j], Al[i], b0h, b1h);
                }
            }
        }
        // NOTE: no trailing barrier — double-buffered stages make it redundant:
        // stores(c+2) and MMA(c) hit the same buffer but are separated by
        // sync(c+1) in every thread's program order.
    }

    // ---- epilogue: + base + W1·t, leaky 0.01 -> g_h[p][b][o] ----
    const int g = lane >> 2, tc = lane & 3;
    #pragma unroll
    for (int i = 0; i < 2; i++) {
        #pragma unroll
        for (int r = 0; r < 2; r++) {
            int o = m0 + w * 32 + i * 16 + r * 8 + g;
            if (o >= I2D) continue;
            float bs = g_base[p * I2D + o];
            const float* w1r = W1 + (size_t)(p * I2D + o) * TTEMP;
            float4 wa = *(const float4*)(w1r);
            float4 wb = *(const float4*)(w1r + 4);
            #pragma unroll
            for (int j = 0; j < 4; j++) {
                #pragma unroll
                for (int cc = 0; cc < 2; cc++) {
                    int b = j * 8 + tc * 2 + cc;
                    const float* tb = s_t + b * 9;
                    float v = acc[i][j][r * 2 + cc] + bs;
                    v += wa.x * tb[0] + wa.y * tb[1] + wa.z * tb[2] + wa.w * tb[3]
                       + wb.x * tb[4] + wb.y * tb[5] + wb.z * tb[6] + wb.w * tb[7];
                    v = v > 0.f ? v : 0.01f * v;
                    g_h[(size_t)(p * BB + b) * I2D + o] = v;
                }
            }
        }
    }
}

// ========== kernel 3: z partials, split-K x 8 (SIMT f32x2, unchanged/passing) ==========
#define APITCH 36
#define ABUF   (128 * APITCH)
#define BOFF   (2 * ABUF)
#define BBUF   (32 * APITCH)
#define SMEMF  (BOFF + 2 * BBUF)

__global__ void __launch_bounds__(128, 3)
k_z(const float* __restrict__ W3) {
    const int s = blockIdx.x, p = blockIdx.y, tid = threadIdx.x;
    const int kbase = s * 288;
    const int kend = (s == 7) ? I2D : (kbase + 288);
    const int NCH = (s == 7) ? 10 : 9;
    __shared__ __align__(16) float smz[SMEMF];
    const uint32_t smaddr = (uint32_t)__cvta_generic_to_shared(smz);

    const int lane = tid & 31, wrp = tid >> 5;
    const int lrow = lane >> 3, akk = (lane & 7) * 4;
    const float* W3p = W3 + (size_t)p * WWID * I2D;
    const float* Hp = g_h + (size_t)p * BB * I2D;

    auto ldrow = [&](const float* basep, int row, int c, uint32_t doff) {
        int kk = kbase + c * 32 + akk;
        int vb = (kend - kk) * 4; vb = vb < 0 ? 0 : (vb > 16 ? 16 : vb);
        int kc = kk <= (I2D - 4) ? kk : (I2D - 4);
        cp16(smaddr + doff * 4, basep + (size_t)row * I2D + kc, vb);
    };
    auto loadA = [&](int c, int buf) {
        #pragma unroll
        for (int i = 0; i < 8; i++) {
            int row = wrp * 32 + i * 4 + lrow;
            ldrow(W3p, row, c, (uint32_t)(buf * ABUF + row * APITCH + akk));
        }
    };
    auto loadB = [&](int c, int buf) {
        #pragma unroll
        for (int i = 0; i < 2; i++) {
            int b = wrp * 8 + i * 4 + lrow;
            ldrow(Hp, b, c, (uint32_t)(BOFF + buf * BBUF + b * APITCH + akk));
        }
    };

    unsigned long long acc[8][4];
    #pragma unroll
    for (int i = 0; i < 8; i++)
        #pragma unroll
        for (int j = 0; j < 4; j++) acc[i][j] = 0ull;

    loadA(0, 0); loadB(0, 0); cp_commit();
    loadA(1, 1); loadB(1, 1); cp_commit();

    const int tm = tid >> 3, tn = tid & 7;
    for (int c = 0; c < NCH; c++) {
        cp_wait1();
        __syncthreads();
        const unsigned long long* Ap = (const unsigned long long*)(smz + (c & 1) * ABUF);
        const unsigned long long* Bp = (const unsigned long long*)(smz + BOFF + (c & 1) * BBUF);
        #pragma unroll
        for (int kp = 0; kp < 16; kp++) {
            unsigned long long av[8], bv[4];
            #pragma unroll
            for (int i = 0; i < 8; i++) av[i] = Ap[(tm + i * 16) * (APITCH / 2) + kp];
            #pragma unroll
            for (int j = 0; j < 4; j++) bv[j] = Bp[(tn + j * 8) * (APITCH / 2) + kp];
            #pragma unroll
            for (int i = 0; i < 8; i++)
                #pragma unroll
                for (int j = 0; j < 4; j++) acc[i][j] = ffma2(av[i], bv[j], acc[i][j]);
        }
        __syncthreads();
        if (c + 2 < NCH) { loadA(c + 2, c & 1); loadB(c + 2, c & 1); }
        cp_commit();
    }

    float* zp = g_zp + (size_t)(p * 8 + s) * BB * WWID;
    #pragma unroll
    for (int i = 0; i < 8; i++) {
        int ww = tm + i * 16;
        #pragma unroll
        for (int j = 0; j < 4; j++) {
            int b = tn + j * 8;
            zp[b * WWID + ww] = flo(acc[i][j]) + fhi(acc[i][j]);
        }
    }
}

// ========== kernel 4: reduce partials + bias + relu + weighted gather ==========
__global__ void k_wx(const float* __restrict__ x, const float* __restrict__ b3) {
    const int p = blockIdx.x, b = blockIdx.y, w = threadIdx.x;
    const int lane = w & 31, wrp = w >> 5;
    __shared__ float red[32];
    float z = b3[p * WWID + w];
    #pragma unroll
    for (int s = 0; s < 8; s++)
        z += g_zp[((size_t)(p * 8 + s) * BB + b) * WWID + w];
    z = z > 0.f ? z : 0.f;
    const float4* xr = (const float4*)(x + ((size_t)b * NNODE + p * WWID + w) * DDIM);
    float4 xa = xr[0], xb = xr[1];
    float v[8] = {z * xa.x, z * xa.y, z * xa.z, z * xa.w,
                  z * xb.x, z * xb.y, z * xb.z, z * xb.w};
    #pragma unroll
    for (int d = 0; d < 8; d++)
        #pragma unroll
        for (int o = 16; o > 0; o >>= 1) v[d] += __shfl_xor_sync(0xffffffffu, v[d], o);
    if (lane < 8) red[wrp * 8 + lane] = v[lane];
    __syncthreads();
    if (w < 8)
        g_wx[((size_t)b * PPART + p) * DDIM + w] =
            red[w] + red[8 + w] + red[16 + w] + red[24 + w];
}

// ========== kernel 5: conv + leaky 0.02 ==========
__global__ void k_y(const float* __restrict__ cw, const float* __restrict__ cb,
                    float* __restrict__ out) {
    const int b = blockIdx.x, l = threadIdx.x;
    const float* wxb = g_wx + (size_t)b * PPART * DDIM;
    float acc = cb[l];
    #pragma unroll 4
    for (int p = 0; p < PPART; p++)
        #pragma unroll
        for (int d = 0; d < 8; d++)
            acc += wxb[p * DDIM + d] * cw[l * (DDIM * PPART) + d * PPART + p];
    out[b * LL2 + l] = acc > 0.f ? acc : 0.02f * acc;
}

extern "C" void kernel_launch(void* const* d_in, const int* in_sizes, int n_in,
                              void* d_out, int out_size) {
    const float* x    = (const float*)d_in[0];
    const float* t    = (const float*)d_in[1];
    const float* cap  = (const float*)d_in[2];
    // d_in[3] = partition_index (identity; folded into k_wx)
    const float* W0   = (const float*)d_in[4];
    const float* W1   = (const float*)d_in[5];
    const float* b1   = (const float*)d_in[6];
    const float* W2   = (const float*)d_in[7];
    const float* W3   = (const float*)d_in[8];
    const float* b3   = (const float*)d_in[9];
    const float* cw   = (const float*)d_in[10];
    const float* cb   = (const float*)d_in[11];
    const int* nodes  = (const int*)d_in[12];
    float* out = (float*)d_out;

    const int dsm = 2 * STAGE;   // 51200 B
    cudaFuncSetAttribute(k_main_mma, cudaFuncAttributeMaxDynamicSharedMemorySize, dsm);

    k_base<<<(PPART * I2D + 7) / 8, 256>>>(W2, b1, cap);
    k_main_mma<<<dim3(19, PPART), 128, dsm>>>(W0, x, t, W1, nodes);
    k_z<<<dim3(8, PPART), 128>>>(W3);
    k_wx<<<dim3(PPART, BB), 128>>>(x, b3);
    k_y<<<BB, LL2>>>(cw, cb, out);
}

// round 7
// speedup vs baseline: 1.4230x; 1.4230x over previous
#include <cuda_runtime.h>
#include <cuda_bf16.h>
#include <cstdint>

#define BB 32
#define NNODE 8192
#define DDIM 8
#define PPART 64
#define WWID 128
#define TTEMP 8
#define LL2 32
#define I2D 2320
#define KDIM 1024

// scratch (no allocs allowed)
__device__ __align__(256) float g_base[PPART * I2D];                // b1 + cap@W2
__device__ __align__(256) float g_h[(size_t)PPART * BB * I2D];      // h as [p][b][o]
__device__ __align__(256) float g_zp[PPART * 8 * BB * WWID];        // split-K partials
__device__ __align__(256) float g_wx[BB * PPART * DDIM];            // [b][p][d]

// ---------------- helpers (SIMT path, k_z) ----------------
__device__ __forceinline__ unsigned long long ffma2(unsigned long long a,
                                                    unsigned long long b,
                                                    unsigned long long c) {
    unsigned long long d;
    asm("fma.rn.f32x2 %0, %1, %2, %3;" : "=l"(d) : "l"(a), "l"(b), "l"(c));
    return d;
}
__device__ __forceinline__ float flo(unsigned long long v) { return __uint_as_float((unsigned)v); }
__device__ __forceinline__ float fhi(unsigned long long v) { return __uint_as_float((unsigned)(v >> 32)); }
__device__ __forceinline__ void cp16(uint32_t dst, const void* src, int szb) {
    asm volatile("cp.async.cg.shared.global [%0], [%1], 16, %2;\n" :: "r"(dst), "l"(src), "r"(szb));
}
__device__ __forceinline__ void cp_commit() { asm volatile("cp.async.commit_group;\n"); }
__device__ __forceinline__ void cp_wait1()  { asm volatile("cp.async.wait_group 1;\n"); }

// ---------------- mma.sync helpers ----------------
#define LDMX4(r, addr) \
    asm volatile("ldmatrix.sync.aligned.m8n8.x4.shared.b16 {%0,%1,%2,%3}, [%4];" \
                 : "=r"((r)[0]), "=r"((r)[1]), "=r"((r)[2]), "=r"((r)[3]) : "r"(addr))

#define MMA16816(d, a, b0, b1) \
    asm volatile("mma.sync.aligned.m16n8k16.row.col.f32.bf16.bf16.f32 " \
                 "{%0,%1,%2,%3}, {%4,%5,%6,%7}, {%8,%9}, {%0,%1,%2,%3};" \
                 : "+f"((d)[0]), "+f"((d)[1]), "+f"((d)[2]), "+f"((d)[3]) \
                 : "r"((a)[0]), "r"((a)[1]), "r"((a)[2]), "r"((a)[3]), "r"(b0), "r"(b1))

#define STS64(addr, r0, r1) \
    asm volatile("st.shared.v2.b32 [%0], {%1,%2};" :: "r"(addr), "r"(r0), "r"(r1) : "memory")

__device__ __forceinline__ uint32_t bfpair(float a, float b) {
    __nv_bfloat162 h = __floats2bfloat162_rn(a, b);
    return *(uint32_t*)&h;
}
__device__ __forceinline__ float bflo(uint32_t u) {
    return __bfloat162float(*(__nv_bfloat16*)&u);
}
__device__ __forceinline__ float bfhi(uint32_t u) {
    uint16_t h = (uint16_t)(u >> 16);
    return __bfloat162float(*(__nv_bfloat16*)&h);
}

// ========== dummy (profiling slot shifter) ==========
__global__ void k_nop() {}

// ========== kernel 1: base[p,o] = b1 + cap(p)·W2[p,o,:] ==========
__global__ void k_base(const float* __restrict__ W2, const float* __restrict__ b1,
                       const float* __restrict__ cap) {
    int idx = blockIdx.x * 8 + (threadIdx.x >> 5);
    if (idx >= PPART * I2D) return;
    int p = idx / I2D, lane = threadIdx.x & 31;
    float4 wv = *(const float4*)(W2 + (size_t)idx * WWID + lane * 4);
    float4 cv = *(const float4*)(cap + p * WWID + lane * 4);
    float acc = wv.x * cv.x + wv.y * cv.y + wv.z * cv.z + wv.w * cv.w;
    #pragma unroll
    for (int o = 16; o > 0; o >>= 1) acc += __shfl_xor_sync(0xffffffffu, acc, o);
    if (lane == 0) g_base[idx] = acc + b1[idx];
}

// ========== kernel 2: h via mma.sync bf16 3-pass split, COALESCED loads ==========
#define PITCHB 40                     // bf16 per row (80 B)
#define A_TILE (128 * PITCHB * 2)     // 10240 B
#define B_TILE (32 * PITCHB * 2)      // 2560 B
#define OFF_AH 0
#define OFF_AL A_TILE
#define OFF_BH (2 * A_TILE)
#define OFF_BL (2 * A_TILE + B_TILE)
#define STAGE  (2 * A_TILE + 2 * B_TILE)   // 25600 B

__global__ void __launch_bounds__(128, 2)
k_main_mma(const float* __restrict__ W0, const float* __restrict__ x,
           const float* __restrict__ t, const float* __restrict__ W1,
           const int* __restrict__ nodes) {
    const int p = blockIdx.y, m0 = blockIdx.x * 128;
    const int tid = threadIdx.x, w = tid >> 5, lane = tid & 31;
    extern __shared__ char sm[];
    __shared__ float s_t[BB * 9];
    __shared__ int s_nodes[WWID];
    const uint32_t smb = (uint32_t)__cvta_generic_to_shared(sm);

    for (int i = tid; i < BB * TTEMP; i += 128) s_t[(i >> 3) * 9 + (i & 7)] = t[i];
    if (tid < WWID) s_nodes[tid] = nodes[p * WWID + tid];
    __syncthreads();

    // Coalesced ownership: thread -> (rows arow0+16q, 16B col window acw)
    const int arow0 = tid >> 3, acw = tid & 7;
    const float* W0p = W0 + (size_t)p * I2D * KDIM;
    const float* arp[8];
    #pragma unroll
    for (int q = 0; q < 8; q++) {
        int m = m0 + arow0 + 16 * q;
        m = (m < I2D) ? m : (I2D - 1);
        arp[q] = W0p + (size_t)m * KDIM + acw * 4;
    }
    // B: rows arow0, arow0+16; col window acw (gathered by node)
    const float* xb0 = x + (size_t)arow0 * (NNODE * DDIM);
    const float* xb1 = x + (size_t)(arow0 + 16) * (NNODE * DDIM);
    const int nidx = (acw >> 1), noff = (acw & 1) * 4;

    float4 ra[8];
    float4 rb[2];
    #pragma unroll
    for (int q = 0; q < 8; q++) ra[q] = *(const float4*)(arp[q]);
    {
        int node = s_nodes[nidx];
        rb[0] = *(const float4*)(xb0 + node * 8 + noff);
        rb[1] = *(const float4*)(xb1 + node * 8 + noff);
    }

    float acc[2][4][4];
    #pragma unroll
    for (int i = 0; i < 2; i++)
        #pragma unroll
        for (int j = 0; j < 4; j++)
            #pragma unroll
            for (int r = 0; r < 4; r++) acc[i][j][r] = 0.f;

    for (int c = 0; c < 32; c++) {
        const uint32_t bufo = smb + (uint32_t)(c & 1) * STAGE;

        // ---- convert + store A: thread's 8 float4s (8 rows, same col window) ----
        #pragma unroll
        for (int q = 0; q < 8; q++) {
            float4 v = ra[q];
            uint32_t h0 = bfpair(v.x, v.y), h1 = bfpair(v.z, v.w);
            uint32_t l0 = bfpair(v.x - bflo(h0), v.y - bfhi(h0));
            uint32_t l1 = bfpair(v.z - bflo(h1), v.w - bfhi(h1));
            uint32_t ao = bufo + (uint32_t)((arow0 + 16 * q) * PITCHB + acw * 4) * 2;
            STS64(ao + OFF_AH, h0, h1);
            STS64(ao + OFF_AL, l0, l1);
        }
        // ---- convert + store B: thread's 2 float4s ----
        #pragma unroll
        for (int q = 0; q < 2; q++) {
            float4 v = rb[q];
            uint32_t h0 = bfpair(v.x, v.y), h1 = bfpair(v.z, v.w);
            uint32_t l0 = bfpair(v.x - bflo(h0), v.y - bfhi(h0));
            uint32_t l1 = bfpair(v.z - bflo(h1), v.w - bfhi(h1));
            uint32_t bo = bufo + (uint32_t)((arow0 + 16 * q) * PITCHB + acw * 4) * 2;
            STS64(bo + OFF_BH, h0, h1);
            STS64(bo + OFF_BL, l0, l1);
        }

        // ---- prefetch chunk c+1 (coalesced: nL=4 per warp-LDG) ----
        {
            int cn = (c < 31) ? (c + 1) : 31;
            #pragma unroll
            for (int q = 0; q < 8; q++)
                ra[q] = *(const float4*)(arp[q] + cn * 32);
            int node = s_nodes[cn * 4 + nidx];
            rb[0] = *(const float4*)(xb0 + node * 8 + noff);
            rb[1] = *(const float4*)(xb1 + node * 8 + noff);
        }

        __syncthreads();

        // ---- MMA: 2 ksteps of k16, 3 passes (hh, hl, lh) ----
        #pragma unroll
        for (int s = 0; s < 2; s++) {
            uint32_t Ah[2][4], Al[2][4], Bh[2][4], Bl[2][4];
            #pragma unroll
            for (int i = 0; i < 2; i++) {
                int row = w * 32 + i * 16 + (lane & 7) + ((lane >> 3) & 1) * 8;
                int col = s * 16 + (lane >> 4) * 8;
                uint32_t ah = bufo + OFF_AH + (uint32_t)(row * PITCHB + col) * 2;
                LDMX4(Ah[i], ah);
                LDMX4(Al[i], ah + (OFF_AL - OFF_AH));
            }
            #pragma unroll
            for (int q = 0; q < 2; q++) {
                int row = q * 16 + (lane >> 4) * 8 + (lane & 7);
                int col = s * 16 + ((lane >> 3) & 1) * 8;
                uint32_t bh = bufo + OFF_BH + (uint32_t)(row * PITCHB + col) * 2;
                LDMX4(Bh[q], bh);
                LDMX4(Bl[q], bh + (OFF_BL - OFF_BH));
            }
            #pragma unroll
            for (int j = 0; j < 4; j++) {
                uint32_t b0h = Bh[j >> 1][(j & 1) * 2], b1h = Bh[j >> 1][(j & 1) * 2 + 1];
                uint32_t b0l = Bl[j >> 1][(j & 1) * 2], b1l = Bl[j >> 1][(j & 1) * 2 + 1];
                #pragma unroll
                for (int i = 0; i < 2; i++) {
                    MMA16816(acc[i][j], Ah[i], b0h, b1h);
                    MMA16816(acc[i][j], Ah[i], b0l, b1l);
                    MMA16816(acc[i][j], Al[i], b0h, b1h);
                }
            }
        }
        // no trailing barrier: double-buffered stages make it redundant
        // (stores(c+2) vs MMA(c) separated by sync(c+1) in program order).
    }

    // ---- epilogue: + base + W1·t, leaky 0.01 -> g_h[p][b][o] ----
    const int g = lane >> 2, tc = lane & 3;
    #pragma unroll
    for (int i = 0; i < 2; i++) {
        #pragma unroll
        for (int r = 0; r < 2; r++) {
            int o = m0 + w * 32 + i * 16 + r * 8 + g;
            if (o >= I2D) continue;
            float bs = g_base[p * I2D + o];
            const float* w1r = W1 + (size_t)(p * I2D + o) * TTEMP;
            float4 wa = *(const float4*)(w1r);
            float4 wb = *(const float4*)(w1r + 4);
            #pragma unroll
            for (int j = 0; j < 4; j++) {
                #pragma unroll
                for (int cc = 0; cc < 2; cc++) {
                    int b = j * 8 + tc * 2 + cc;
                    const float* tb = s_t + b * 9;
                    float v = acc[i][j][r * 2 + cc] + bs;
                    v += wa.x * tb[0] + wa.y * tb[1] + wa.z * tb[2] + wa.w * tb[3]
                       + wb.x * tb[4] + wb.y * tb[5] + wb.z * tb[6] + wb.w * tb[7];
                    v = v > 0.f ? v : 0.01f * v;
                    g_h[(size_t)(p * BB + b) * I2D + o] = v;
                }
            }
        }
    }
}

// ========== kernel 3: z partials, split-K x 8 (SIMT f32x2, unchanged/passing) ==========
#define APITCH 36
#define ABUF   (128 * APITCH)
#define BOFF   (2 * ABUF)
#define BBUF   (32 * APITCH)
#define SMEMF  (BOFF + 2 * BBUF)

__global__ void __launch_bounds__(128, 3)
k_z(const float* __restrict__ W3) {
    const int s = blockIdx.x, p = blockIdx.y, tid = threadIdx.x;
    const int kbase = s * 288;
    const int kend = (s == 7) ? I2D : (kbase + 288);
    const int NCH = (s == 7) ? 10 : 9;
    __shared__ __align__(16) float smz[SMEMF];
    const uint32_t smaddr = (uint32_t)__cvta_generic_to_shared(smz);

    const int lane = tid & 31, wrp = tid >> 5;
    const int lrow = lane >> 3, akk = (lane & 7) * 4;
    const float* W3p = W3 + (size_t)p * WWID * I2D;
    const float* Hp = g_h + (size_t)p * BB * I2D;

    auto ldrow = [&](const float* basep, int row, int c, uint32_t doff) {
        int kk = kbase + c * 32 + akk;
        int vb = (kend - kk) * 4; vb = vb < 0 ? 0 : (vb > 16 ? 16 : vb);
        int kc = kk <= (I2D - 4) ? kk : (I2D - 4);
        cp16(smaddr + doff * 4, basep + (size_t)row * I2D + kc, vb);
    };
    auto loadA = [&](int c, int buf) {
        #pragma unroll
        for (int i = 0; i < 8; i++) {
            int row = wrp * 32 + i * 4 + lrow;
            ldrow(W3p, row, c, (uint32_t)(buf * ABUF + row * APITCH + akk));
        }
    };
    auto loadB = [&](int c, int buf) {
        #pragma unroll
        for (int i = 0; i < 2; i++) {
            int b = wrp * 8 + i * 4 + lrow;
            ldrow(Hp, b, c, (uint32_t)(BOFF + buf * BBUF + b * APITCH + akk));
        }
    };

    unsigned long long acc[8][4];
    #pragma unroll
    for (int i = 0; i < 8; i++)
        #pragma unroll
        for (int j = 0; j < 4; j++) acc[i][j] = 0ull;

    loadA(0, 0); loadB(0, 0); cp_commit();
    loadA(1, 1); loadB(1, 1); cp_commit();

    const int tm = tid >> 3, tn = tid & 7;
    for (int c = 0; c < NCH; c++) {
        cp_wait1();
        __syncthreads();
        const unsigned long long* Ap = (const unsigned long long*)(smz + (c & 1) * ABUF);
        const unsigned long long* Bp = (const unsigned long long*)(smz + BOFF + (c & 1) * BBUF);
        #pragma unroll
        for (int kp = 0; kp < 16; kp++) {
            unsigned long long av[8], bv[4];
            #pragma unroll
            for (int i = 0; i < 8; i++) av[i] = Ap[(tm + i * 16) * (APITCH / 2) + kp];
            #pragma unroll
            for (int j = 0; j < 4; j++) bv[j] = Bp[(tn + j * 8) * (APITCH / 2) + kp];
            #pragma unroll
            for (int i = 0; i < 8; i++)
                #pragma unroll
                for (int j = 0; j < 4; j++) acc[i][j] = ffma2(av[i], bv[j], acc[i][j]);
        }
        __syncthreads();
        if (c + 2 < NCH) { loadA(c + 2, c & 1); loadB(c + 2, c & 1); }
        cp_commit();
    }

    float* zp = g_zp + (size_t)(p * 8 + s) * BB * WWID;
    #pragma unroll
    for (int i = 0; i < 8; i++) {
        int ww = tm + i * 16;
        #pragma unroll
        for (int j = 0; j < 4; j++) {
            int b = tn + j * 8;
            zp[b * WWID + ww] = flo(acc[i][j]) + fhi(acc[i][j]);
        }
    }
}

// ========== kernel 4: reduce partials + bias + relu + weighted gather ==========
__global__ void k_wx(const float* __restrict__ x, const float* __restrict__ b3) {
    const int p = blockIdx.x, b = blockIdx.y, w = threadIdx.x;
    const int lane = w & 31, wrp = w >> 5;
    __shared__ float red[32];
    float z = b3[p * WWID + w];
    #pragma unroll
    for (int s = 0; s < 8; s++)
        z += g_zp[((size_t)(p * 8 + s) * BB + b) * WWID + w];
    z = z > 0.f ? z : 0.f;
    const float4* xr = (const float4*)(x + ((size_t)b * NNODE + p * WWID + w) * DDIM);
    float4 xa = xr[0], xb = xr[1];
    float v[8] = {z * xa.x, z * xa.y, z * xa.z, z * xa.w,
                  z * xb.x, z * xb.y, z * xb.z, z * xb.w};
    #pragma unroll
    for (int d = 0; d < 8; d++)
        #pragma unroll
        for (int o = 16; o > 0; o >>= 1) v[d] += __shfl_xor_sync(0xffffffffu, v[d], o);
    if (lane < 8) red[wrp * 8 + lane] = v[lane];
    __syncthreads();
    if (w < 8)
        g_wx[((size_t)b * PPART + p) * DDIM + w] =
            red[w] + red[8 + w] + red[16 + w] + red[24 + w];
}

// ========== kernel 5: conv + leaky 0.02 ==========
__global__ void k_y(const float* __restrict__ cw, const float* __restrict__ cb,
                    float* __restrict__ out) {
    const int b = blockIdx.x, l = threadIdx.x;
    const float* wxb = g_wx + (size_t)b * PPART * DDIM;
    float acc = cb[l];
    #pragma unroll 4
    for (int p = 0; p < PPART; p++)
        #pragma unroll
        for (int d = 0; d < 8; d++)
            acc += wxb[p * DDIM + d] * cw[l * (DDIM * PPART) + d * PPART + p];
    out[b * LL2 + l] = acc > 0.f ? acc : 0.02f * acc;
}

extern "C" void kernel_launch(void* const* d_in, const int* in_sizes, int n_in,
                              void* d_out, int out_size) {
    const float* x    = (const float*)d_in[0];
    const float* t    = (const float*)d_in[1];
    const float* cap  = (const float*)d_in[2];
    // d_in[3] = partition_index (identity; folded into k_wx)
    const float* W0   = (const float*)d_in[4];
    const float* W1   = (const float*)d_in[5];
    const float* b1   = (const float*)d_in[6];
    const float* W2   = (const float*)d_in[7];
    const float* W3   = (const float*)d_in[8];
    const float* b3   = (const float*)d_in[9];
    const float* cw   = (const float*)d_in[10];
    const float* cb   = (const float*)d_in[11];
    const int* nodes  = (const int*)d_in[12];
    float* out = (float*)d_out;

    const int dsm = 2 * STAGE;   // 51200 B
    cudaFuncSetAttribute(k_main_mma, cudaFuncAttributeMaxDynamicSharedMemorySize, dsm);

    // two no-op launches shift the ncu capture slot (currently position 4 = k_wx)
    // onto k_main.
    k_nop<<<1, 32>>>();
    k_nop<<<1, 32>>>();
    k_base<<<(PPART * I2D + 7) / 8, 256>>>(W2, b1, cap);
    k_main_mma<<<dim3(19, PPART), 128, dsm>>>(W0, x, t, W1, nodes);
    k_z<<<dim3(8, PPART), 128>>>(W3);
    k_wx<<<dim3(PPART, BB), 128>>>(x, b3);
    k_y<<<BB, LL2>>>(cw, cb, out);
}

// round 8
// speedup vs baseline: 1.4232x; 1.0001x over previous
#include <cuda_runtime.h>
#include <cuda_bf16.h>
#include <cstdint>

#define BB 32
#define NNODE 8192
#define DDIM 8
#define PPART 64
#define WWID 128
#define TTEMP 8
#define LL2 32
#define I2D 2320
#define KDIM 1024

// scratch (no allocs allowed)
__device__ __align__(256) float g_base[PPART * I2D];                // b1 + cap@W2
__device__ __align__(256) float g_h[(size_t)PPART * BB * I2D];      // h as [p][b][o]
__device__ __align__(256) float g_zp[PPART * 8 * BB * WWID];        // split-K partials
__device__ __align__(256) float g_wx[BB * PPART * DDIM];            // [b][p][d]

// ---------------- helpers (SIMT path, k_z) ----------------
__device__ __forceinline__ unsigned long long ffma2(unsigned long long a,
                                                    unsigned long long b,
                                                    unsigned long long c) {
    unsigned long long d;
    asm("fma.rn.f32x2 %0, %1, %2, %3;" : "=l"(d) : "l"(a), "l"(b), "l"(c));
    return d;
}
__device__ __forceinline__ float flo(unsigned long long v) { return __uint_as_float((unsigned)v); }
__device__ __forceinline__ float fhi(unsigned long long v) { return __uint_as_float((unsigned)(v >> 32)); }
__device__ __forceinline__ void cp16(uint32_t dst, const void* src, int szb) {
    asm volatile("cp.async.cg.shared.global [%0], [%1], 16, %2;\n" :: "r"(dst), "l"(src), "r"(szb));
}
__device__ __forceinline__ void cp_commit() { asm volatile("cp.async.commit_group;\n"); }
__device__ __forceinline__ void cp_wait1()  { asm volatile("cp.async.wait_group 1;\n"); }

// ---------------- mma.sync helpers ----------------
#define LDMX4(r, addr) \
    asm volatile("ldmatrix.sync.aligned.m8n8.x4.shared.b16 {%0,%1,%2,%3}, [%4];" \
                 : "=r"((r)[0]), "=r"((r)[1]), "=r"((r)[2]), "=r"((r)[3]) : "r"(addr))

#define MMA16816(d, a, b0, b1) \
    asm volatile("mma.sync.aligned.m16n8k16.row.col.f32.bf16.bf16.f32 " \
                 "{%0,%1,%2,%3}, {%4,%5,%6,%7}, {%8,%9}, {%0,%1,%2,%3};" \
                 : "+f"((d)[0]), "+f"((d)[1]), "+f"((d)[2]), "+f"((d)[3]) \
                 : "r"((a)[0]), "r"((a)[1]), "r"((a)[2]), "r"((a)[3]), "r"(b0), "r"(b1))

#define STS64(addr, r0, r1) \
    asm volatile("st.shared.v2.b32 [%0], {%1,%2};" :: "r"(addr), "r"(r0), "r"(r1) : "memory")

__device__ __forceinline__ uint32_t bfpair(float a, float b) {
    __nv_bfloat162 h = __floats2bfloat162_rn(a, b);
    return *(uint32_t*)&h;
}
__device__ __forceinline__ float bflo(uint32_t u) {
    return __bfloat162float(*(__nv_bfloat16*)&u);
}
__device__ __forceinline__ float bfhi(uint32_t u) {
    uint16_t h = (uint16_t)(u >> 16);
    return __bfloat162float(*(__nv_bfloat16*)&h);
}

// ========== dummy (profiling slot shifter) ==========
__global__ void k_nop() {}

// ========== kernel 1: base[p,o] = b1 + cap(p)·W2[p,o,:] ==========
__global__ void k_base(const float* __restrict__ W2, const float* __restrict__ b1,
                       const float* __restrict__ cap) {
    int idx = blockIdx.x * 8 + (threadIdx.x >> 5);
    if (idx >= PPART * I2D) return;
    int p = idx / I2D, lane = threadIdx.x & 31;
    float4 wv = *(const float4*)(W2 + (size_t)idx * WWID + lane * 4);
    float4 cv = *(const float4*)(cap + p * WWID + lane * 4);
    float acc = wv.x * cv.x + wv.y * cv.y + wv.z * cv.z + wv.w * cv.w;
    #pragma unroll
    for (int o = 16; o > 0; o >>= 1) acc += __shfl_xor_sync(0xffffffffu, acc, o);
    if (lane == 0) g_base[idx] = acc + b1[idx];
}

// ========== kernel 2: h via mma.sync bf16 3-pass split, coalesced, 3 CTAs/SM ==========
#define PITCHB 40                     // bf16 per row (80 B)
#define A_TILE (128 * PITCHB * 2)     // 10240 B
#define B_TILE (32 * PITCHB * 2)      // 2560 B
#define OFF_AH 0
#define OFF_AL A_TILE
#define OFF_BH (2 * A_TILE)
#define OFF_BL (2 * A_TILE + B_TILE)
#define STAGE  (2 * A_TILE + 2 * B_TILE)   // 25600 B

__global__ void __launch_bounds__(128, 3)
k_main_mma(const float* __restrict__ W0, const float* __restrict__ x,
           const float* __restrict__ t, const float* __restrict__ W1,
           const int* __restrict__ nodes) {
    const int p = blockIdx.y, m0 = blockIdx.x * 128;
    const int tid = threadIdx.x, w = tid >> 5, lane = tid & 31;
    extern __shared__ char sm[];
    __shared__ float s_t[BB * 9];
    __shared__ int s_nodes[WWID];
    const uint32_t smb = (uint32_t)__cvta_generic_to_shared(sm);

    for (int i = tid; i < BB * TTEMP; i += 128) s_t[(i >> 3) * 9 + (i & 7)] = t[i];
    if (tid < WWID) s_nodes[tid] = nodes[p * WWID + tid];
    __syncthreads();

    // Coalesced ownership: thread -> (rows arow0+16q, 16B col window acw)
    const int arow0 = tid >> 3, acw = tid & 7;
    const float* W0p = W0 + (size_t)p * I2D * KDIM;
    const float* arp[8];
    #pragma unroll
    for (int q = 0; q < 8; q++) {
        int m = m0 + arow0 + 16 * q;
        m = (m < I2D) ? m : (I2D - 1);
        arp[q] = W0p + (size_t)m * KDIM + acw * 4;
    }
    // B: rows arow0, arow0+16; col window acw (gathered by node)
    const float* xb0 = x + (size_t)arow0 * (NNODE * DDIM);
    const float* xb1 = x + (size_t)(arow0 + 16) * (NNODE * DDIM);
    const int nidx = (acw >> 1), noff = (acw & 1) * 4;

    float4 ra[8];
    float4 rb[2];
    #pragma unroll
    for (int q = 0; q < 8; q++) ra[q] = *(const float4*)(arp[q]);
    {
        int node = s_nodes[nidx];
        rb[0] = *(const float4*)(xb0 + node * 8 + noff);
        rb[1] = *(const float4*)(xb1 + node * 8 + noff);
    }

    float acc[2][4][4];
    #pragma unroll
    for (int i = 0; i < 2; i++)
        #pragma unroll
        for (int j = 0; j < 4; j++)
            #pragma unroll
            for (int r = 0; r < 4; r++) acc[i][j][r] = 0.f;

    for (int c = 0; c < 32; c++) {
        const uint32_t bufo = smb + (uint32_t)(c & 1) * STAGE;

        // ---- convert + store A: thread's 8 float4s (8 rows, same col window) ----
        #pragma unroll
        for (int q = 0; q < 8; q++) {
            float4 v = ra[q];
            uint32_t h0 = bfpair(v.x, v.y), h1 = bfpair(v.z, v.w);
            uint32_t l0 = bfpair(v.x - bflo(h0), v.y - bfhi(h0));
            uint32_t l1 = bfpair(v.z - bflo(h1), v.w - bfhi(h1));
            uint32_t ao = bufo + (uint32_t)((arow0 + 16 * q) * PITCHB + acw * 4) * 2;
            STS64(ao + OFF_AH, h0, h1);
            STS64(ao + OFF_AL, l0, l1);
        }
        // ---- convert + store B: thread's 2 float4s ----
        #pragma unroll
        for (int q = 0; q < 2; q++) {
            float4 v = rb[q];
            uint32_t h0 = bfpair(v.x, v.y), h1 = bfpair(v.z, v.w);
            uint32_t l0 = bfpair(v.x - bflo(h0), v.y - bfhi(h0));
            uint32_t l1 = bfpair(v.z - bflo(h1), v.w - bfhi(h1));
            uint32_t bo = bufo + (uint32_t)((arow0 + 16 * q) * PITCHB + acw * 4) * 2;
            STS64(bo + OFF_BH, h0, h1);
            STS64(bo + OFF_BL, l0, l1);
        }

        // ---- prefetch chunk c+1 (coalesced: nL=4 per warp-LDG) ----
        {
            int cn = (c < 31) ? (c + 1) : 31;
            #pragma unroll
            for (int q = 0; q < 8; q++)
                ra[q] = *(const float4*)(arp[q] + cn * 32);
            int node = s_nodes[cn * 4 + nidx];
            rb[0] = *(const float4*)(xb0 + node * 8 + noff);
            rb[1] = *(const float4*)(xb1 + node * 8 + noff);
        }

        __syncthreads();

        // ---- MMA: 2 ksteps of k16, 3 passes (hh, hl, lh) ----
        #pragma unroll
        for (int s = 0; s < 2; s++) {
            uint32_t Ah[2][4], Al[2][4], Bh[2][4], Bl[2][4];
            #pragma unroll
            for (int i = 0; i < 2; i++) {
                int row = w * 32 + i * 16 + (lane & 7) + ((lane >> 3) & 1) * 8;
                int col = s * 16 + (lane >> 4) * 8;
                uint32_t ah = bufo + OFF_AH + (uint32_t)(row * PITCHB + col) * 2;
                LDMX4(Ah[i], ah);
                LDMX4(Al[i], ah + (OFF_AL - OFF_AH));
            }
            #pragma unroll
            for (int q = 0; q < 2; q++) {
                int row = q * 16 + (lane >> 4) * 8 + (lane & 7);
                int col = s * 16 + ((lane >> 3) & 1) * 8;
                uint32_t bh = bufo + OFF_BH + (uint32_t)(row * PITCHB + col) * 2;
                LDMX4(Bh[q], bh);
                LDMX4(Bl[q], bh + (OFF_BL - OFF_BH));
            }
            #pragma unroll
            for (int j = 0; j < 4; j++) {
                uint32_t b0h = Bh[j >> 1][(j & 1) * 2], b1h = Bh[j >> 1][(j & 1) * 2 + 1];
                uint32_t b0l = Bl[j >> 1][(j & 1) * 2], b1l = Bl[j >> 1][(j & 1) * 2 + 1];
                #pragma unroll
                for (int i = 0; i < 2; i++) {
                    MMA16816(acc[i][j], Ah[i], b0h, b1h);
                    MMA16816(acc[i][j], Ah[i], b0l, b1l);
                    MMA16816(acc[i][j], Al[i], b0h, b1h);
                }
            }
        }
        // no trailing barrier: double-buffered stages make it redundant
        // (stores(c+2) vs MMA(c) separated by sync(c+1) in program order).
    }

    // ---- epilogue: + base + W1·t, leaky 0.01 -> g_h[p][b][o] ----
    const int g = lane >> 2, tc = lane & 3;
    #pragma unroll
    for (int i = 0; i < 2; i++) {
        #pragma unroll
        for (int r = 0; r < 2; r++) {
            int o = m0 + w * 32 + i * 16 + r * 8 + g;
            if (o >= I2D) continue;
            float bs = g_base[p * I2D + o];
            const float* w1r = W1 + (size_t)(p * I2D + o) * TTEMP;
            float4 wa = *(const float4*)(w1r);
            float4 wb = *(const float4*)(w1r + 4);
            #pragma unroll
            for (int j = 0; j < 4; j++) {
                #pragma unroll
                for (int cc = 0; cc < 2; cc++) {
                    int b = j * 8 + tc * 2 + cc;
                    const float* tb = s_t + b * 9;
                    float v = acc[i][j][r * 2 + cc] + bs;
                    v += wa.x * tb[0] + wa.y * tb[1] + wa.z * tb[2] + wa.w * tb[3]
                       + wb.x * tb[4] + wb.y * tb[5] + wb.z * tb[6] + wb.w * tb[7];
                    v = v > 0.f ? v : 0.01f * v;
                    g_h[(size_t)(p * BB + b) * I2D + o] = v;
                }
            }
        }
    }
}

// ========== kernel 3: z partials, split-K x 8 (SIMT f32x2, unchanged/passing) ==========
#define APITCH 36
#define ABUF   (128 * APITCH)
#define BOFF   (2 * ABUF)
#define BBUF   (32 * APITCH)
#define SMEMF  (BOFF + 2 * BBUF)

__global__ void __launch_bounds__(128, 3)
k_z(const float* __restrict__ W3) {
    const int s = blockIdx.x, p = blockIdx.y, tid = threadIdx.x;
    const int kbase = s * 288;
    const int kend = (s == 7) ? I2D : (kbase + 288);
    const int NCH = (s == 7) ? 10 : 9;
    __shared__ __align__(16) float smz[SMEMF];
    const uint32_t smaddr = (uint32_t)__cvta_generic_to_shared(smz);

    const int lane = tid & 31, wrp = tid >> 5;
    const int lrow = lane >> 3, akk = (lane & 7) * 4;
    const float* W3p = W3 + (size_t)p * WWID * I2D;
    const float* Hp = g_h + (size_t)p * BB * I2D;

    auto ldrow = [&](const float* basep, int row, int c, uint32_t doff) {
        int kk = kbase + c * 32 + akk;
        int vb = (kend - kk) * 4; vb = vb < 0 ? 0 : (vb > 16 ? 16 : vb);
        int kc = kk <= (I2D - 4) ? kk : (I2D - 4);
        cp16(smaddr + doff * 4, basep + (size_t)row * I2D + kc, vb);
    };
    auto loadA = [&](int c, int buf) {
        #pragma unroll
        for (int i = 0; i < 8; i++) {
            int row = wrp * 32 + i * 4 + lrow;
            ldrow(W3p, row, c, (uint32_t)(buf * ABUF + row * APITCH + akk));
        }
    };
    auto loadB = [&](int c, int buf) {
        #pragma unroll
        for (int i = 0; i < 2; i++) {
            int b = wrp * 8 + i * 4 + lrow;
            ldrow(Hp, b, c, (uint32_t)(BOFF + buf * BBUF + b * APITCH + akk));
        }
    };

    unsigned long long acc[8][4];
    #pragma unroll
    for (int i = 0; i < 8; i++)
        #pragma unroll
        for (int j = 0; j < 4; j++) acc[i][j] = 0ull;

    loadA(0, 0); loadB(0, 0); cp_commit();
    loadA(1, 1); loadB(1, 1); cp_commit();

    const int tm = tid >> 3, tn = tid & 7;
    for (int c = 0; c < NCH; c++) {
        cp_wait1();
        __syncthreads();
        const unsigned long long* Ap = (const unsigned long long*)(smz + (c & 1) * ABUF);
        const unsigned long long* Bp = (const unsigned long long*)(smz + BOFF + (c & 1) * BBUF);
        #pragma unroll
        for (int kp = 0; kp < 16; kp++) {
            unsigned long long av[8], bv[4];
            #pragma unroll
            for (int i = 0; i < 8; i++) av[i] = Ap[(tm + i * 16) * (APITCH / 2) + kp];
            #pragma unroll
            for (int j = 0; j < 4; j++) bv[j] = Bp[(tn + j * 8) * (APITCH / 2) + kp];
            #pragma unroll
            for (int i = 0; i < 8; i++)
                #pragma unroll
                for (int j = 0; j < 4; j++) acc[i][j] = ffma2(av[i], bv[j], acc[i][j]);
        }
        __syncthreads();
        if (c + 2 < NCH) { loadA(c + 2, c & 1); loadB(c + 2, c & 1); }
        cp_commit();
    }

    float* zp = g_zp + (size_t)(p * 8 + s) * BB * WWID;
    #pragma unroll
    for (int i = 0; i < 8; i++) {
        int ww = tm + i * 16;
        #pragma unroll
        for (int j = 0; j < 4; j++) {
            int b = tn + j * 8;
            zp[b * WWID + ww] = flo(acc[i][j]) + fhi(acc[i][j]);
        }
    }
}

// ========== kernel 4: reduce partials + bias + relu + weighted gather ==========
__global__ void k_wx(const float* __restrict__ x, const float* __restrict__ b3) {
    const int p = blockIdx.x, b = blockIdx.y, w = threadIdx.x;
    const int lane = w & 31, wrp = w >> 5;
    __shared__ float red[32];
    float z = b3[p * WWID + w];
    #pragma unroll
    for (int s = 0; s < 8; s++)
        z += g_zp[((size_t)(p * 8 + s) * BB + b) * WWID + w];
    z = z > 0.f ? z : 0.f;
    const float4* xr = (const float4*)(x + ((size_t)b * NNODE + p * WWID + w) * DDIM);
    float4 xa = xr[0], xb = xr[1];
    float v[8] = {z * xa.x, z * xa.y, z * xa.z, z * xa.w,
                  z * xb.x, z * xb.y, z * xb.z, z * xb.w};
    #pragma unroll
    for (int d = 0; d < 8; d++)
        #pragma unroll
        for (int o = 16; o > 0; o >>= 1) v[d] += __shfl_xor_sync(0xffffffffu, v[d], o);
    if (lane < 8) red[wrp * 8 + lane] = v[lane];
    __syncthreads();
    if (w < 8)
        g_wx[((size_t)b * PPART + p) * DDIM + w] =
            red[w] + red[8 + w] + red[16 + w] + red[24 + w];
}

// ========== kernel 5: conv + leaky 0.02 ==========
__global__ void k_y(const float* __restrict__ cw, const float* __restrict__ cb,
                    float* __restrict__ out) {
    const int b = blockIdx.x, l = threadIdx.x;
    const float* wxb = g_wx + (size_t)b * PPART * DDIM;
    float acc = cb[l];
    #pragma unroll 4
    for (int p = 0; p < PPART; p++)
        #pragma unroll
        for (int d = 0; d < 8; d++)
            acc += wxb[p * DDIM + d] * cw[l * (DDIM * PPART) + d * PPART + p];
    out[b * LL2 + l] = acc > 0.f ? acc : 0.02f * acc;
}

extern "C" void kernel_launch(void* const* d_in, const int* in_sizes, int n_in,
                              void* d_out, int out_size) {
    const float* x    = (const float*)d_in[0];
    const float* t    = (const float*)d_in[1];
    const float* cap  = (const float*)d_in[2];
    // d_in[3] = partition_index (identity; folded into k_wx)
    const float* W0   = (const float*)d_in[4];
    const float* W1   = (const float*)d_in[5];
    const float* b1   = (const float*)d_in[6];
    const float* W2   = (const float*)d_in[7];
    const float* W3   = (const float*)d_in[8];
    const float* b3   = (const float*)d_in[9];
    const float* cw   = (const float*)d_in[10];
    const float* cb   = (const float*)d_in[11];
    const int* nodes  = (const int*)d_in[12];
    float* out = (float*)d_out;

    const int dsm = 2 * STAGE;   // 51200 B
    cudaFuncSetAttribute(k_main_mma, cudaFuncAttributeMaxDynamicSharedMemorySize, dsm);

    // two no-op launches keep k_main in the ncu capture slot
    k_nop<<<1, 32>>>();
    k_nop<<<1, 32>>>();
    k_base<<<(PPART * I2D + 7) / 8, 256>>>(W2, b1, cap);
    k_main_mma<<<dim3(19, PPART), 128, dsm>>>(W0, x, t, W1, nodes);
    k_z<<<dim3(8, PPART), 128>>>(W3);
    k_wx<<<dim3(PPART, BB), 128>>>(x, b3);
    k_y<<<BB, LL2>>>(cw, cb, out);
}